// round 8
// baseline (speedup 1.0000x reference)
#include <cuda_runtime.h>
#include <math.h>

#define BS    8
#define NROT  60
#define NPTS  500
#define NBR   (BS * NROT)     // 480
#define HW    6400            // 80*80
#define CHUNK 5               // targets batched per load group (500 = 5*100)

// Scratch (allocation-free: __device__ globals)
__device__ float g_sym[NBR];
__device__ float g_nonsym[NBR];
__device__ float g_scal[2];       // [0] = loss_reg, [1] = loss_t
__device__ unsigned int g_cnt;    // completion counter (reset by last block)

// ---------------------------------------------------------------------------
// Single fused kernel, grid = NBR + 1 blocks of 128 threads.
//  blocks 0..479 : chamfer for one (b, r); 4 pred points per thread, SCALAR FFMA
//  block  480    : reg loss + huber translation loss (runs concurrently)
//  last block to finish: finalize loss_r and combine into out[0..3]
// ---------------------------------------------------------------------------
__global__ __launch_bounds__(128, 4) void fused_kernel(
    const float* __restrict__ pred_t,        // (8,500,3)
    const float* __restrict__ pred_r,        // (8,60,4)
    const float* __restrict__ pred_c,        // (8,60)
    const float* __restrict__ target_r,      // (8,1,500,3)
    const float* __restrict__ target_t,      // (8,3,80,80)
    const float* __restrict__ model_points,  // (8,1,500,3)
    const int*   __restrict__ choose,        // (8,500)
    const int*   __restrict__ symmetric,     // (8,) bool->int32
    const float* __restrict__ diameters,     // (8,)
    const float* __restrict__ rot_anchors,   // (60,4)
    float*       __restrict__ out)           // 4 floats
{
    __shared__ float4 tg[NPTS];    // per target: (-2tx, -2ty, -2tz, |t|^2)
    __shared__ float  redA[4], redB[4];
    __shared__ int    s_last;

    const int tid  = threadIdx.x;
    const int lane = tid & 31;
    const int wid  = tid >> 5;
    const int blk  = blockIdx.x;

    if (blk < NBR) {
        // ================= chamfer block =================
        const int b = blk / NROT;
        const float* tp = target_r + (size_t)b * NPTS * 3;

        for (int m = tid; m < NPTS; m += 128) {
            float tx = tp[3*m], ty = tp[3*m+1], tz = tp[3*m+2];
            tg[m] = make_float4(-2.f*tx, -2.f*ty, -2.f*tz,
                                tx*tx + ty*ty + tz*tz);
        }

        // Rotation matrix from (unnormalized) quaternion, as reference.
        const float* q = pred_r + (size_t)blk * 4;
        float w = q[0], x = q[1], y = q[2], z = q[3];
        float r00 = 1.f - 2.f*(y*y + z*z);
        float r01 = 2.f*x*y - 2.f*w*z;
        float r02 = 2.f*w*y + 2.f*x*z;
        float r10 = 2.f*x*y + 2.f*z*w;
        float r11 = 1.f - 2.f*(x*x + z*z);
        float r12 = -2.f*w*x + 2.f*y*z;
        float r20 = -2.f*w*y + 2.f*x*z;
        float r21 = 2.f*w*x + 2.f*y*z;
        float r22 = 1.f - 2.f*(x*x + y*y);

        __syncthreads();

        // 4 pred points per thread: n = tid + 128*i
        const float* mpb = model_points + (size_t)b * NPTS * 3;
        float px[4], py[4], pz[4], a2[4];
        bool  val[4];
        #pragma unroll
        for (int i = 0; i < 4; i++) {
            int n = tid + 128 * i;
            val[i] = (n < NPTS);
            float mx = 0.f, my = 0.f, mz = 0.f;
            if (val[i]) { mx = mpb[3*n]; my = mpb[3*n+1]; mz = mpb[3*n+2]; }
            px[i] = r00*mx + r01*my + r02*mz;
            py[i] = r10*mx + r11*my + r12*mz;
            pz[i] = r20*mx + r21*my + r22*mz;
            a2[i] = px[i]*px[i] + py[i]*py[i] + pz[i]*pz[i];
        }

        const float INF = 3.4e38f;
        // Two min accumulators per point (chunk-index parity) to break chains.
        float mnA[4] = {INF, INF, INF, INF};
        float mnB[4] = {INF, INF, INF, INF};

        // Scalar inner loop: per target 1 LDS.128 + 4x(3 FFMA + 1 FMNMX).
        for (int j0 = 0; j0 < NPTS; j0 += CHUNK) {
            float4 T[CHUNK];
            #pragma unroll
            for (int k = 0; k < CHUNK; k++) T[k] = tg[j0 + k];
            #pragma unroll
            for (int k = 0; k < CHUNK; k++) {
                #pragma unroll
                for (int i = 0; i < 4; i++) {
                    float s = fmaf(px[i], T[k].x,
                              fmaf(py[i], T[k].y,
                              fmaf(pz[i], T[k].z, T[k].w)));
                    if (k & 1) mnB[i] = fminf(mnB[i], s);
                    else       mnA[i] = fminf(mnA[i], s);
                }
            }
        }

        float symsum = 0.f, nssum = 0.f;
        #pragma unroll
        for (int i = 0; i < 4; i++) {
            if (val[i]) {
                float m = fminf(mnA[i], mnB[i]);
                symsum += sqrtf(fmaxf(a2[i] + m, 1e-12f));
                int n = tid + 128 * i;
                // recover t_n from tg: t = -0.5 * tg.xyz
                float4 t = tg[n];
                float dx = fmaf(0.5f, t.x, px[i]);
                float dy = fmaf(0.5f, t.y, py[i]);
                float dz = fmaf(0.5f, t.z, pz[i]);
                nssum += sqrtf(dx*dx + dy*dy + dz*dz);
            }
        }

        #pragma unroll
        for (int off = 16; off; off >>= 1) {
            symsum += __shfl_down_sync(0xffffffffu, symsum, off);
            nssum  += __shfl_down_sync(0xffffffffu, nssum,  off);
        }
        if (lane == 0) { redA[wid] = symsum; redB[wid] = nssum; }
        __syncthreads();
        if (tid == 0) {
            g_sym[blk]    = (redA[0]+redA[1]+redA[2]+redA[3]) * (1.0f / NPTS);
            g_nonsym[blk] = (redB[0]+redB[1]+redB[2]+redB[3]) * (1.0f / NPTS);
        }
    } else {
        // ================= reg + huber block =================
        float* anc = reinterpret_cast<float*>(tg);  // 240 floats
        for (int i = tid; i < NROT * 4; i += 128) anc[i] = rot_anchors[i];
        __syncthreads();

        float regsum = 0.f;
        for (int i = tid; i < NBR; i += 128) {
            int r = i % NROT;
            float q0 = pred_r[4*i], q1 = pred_r[4*i+1];
            float q2 = pred_r[4*i+2], q3 = pred_r[4*i+3];
            float mx = -3.4e38f, dg = 0.f;
            #pragma unroll 4
            for (int a = 0; a < NROT; a++) {
                float c = q0*anc[4*a] + q1*anc[4*a+1] + q2*anc[4*a+2] + q3*anc[4*a+3];
                mx = fmaxf(mx, c);
                if (a == r) dg = c;
            }
            float reg = mx - dg;
            regsum += (reg > 0.001f) ? reg : 0.f;
        }

        float tsum = 0.f;
        for (int i = tid; i < BS * NPTS; i += 128) {
            int b  = i / NPTS;
            int ch = choose[i];
            const float* tb = target_t + (size_t)b * 3 * HW;
            float tv0 = tb[ch], tv1 = tb[HW + ch], tv2 = tb[2*HW + ch];
            float p0 = pred_t[3*i], p1 = pred_t[3*i+1], p2 = pred_t[3*i+2];
            float d0 = p0 - tv0, d1 = p1 - tv1, d2 = p2 - tv2;
            float a0 = fabsf(d0), a1 = fabsf(d1), a2v = fabsf(d2);
            tsum += (a0 < 1.f) ? 0.5f*d0*d0 : (a0 - 0.5f);
            tsum += (a1 < 1.f) ? 0.5f*d1*d1 : (a1 - 0.5f);
            tsum += (a2v < 1.f) ? 0.5f*d2*d2 : (a2v - 0.5f);
        }

        #pragma unroll
        for (int off = 16; off; off >>= 1) {
            regsum += __shfl_down_sync(0xffffffffu, regsum, off);
            tsum   += __shfl_down_sync(0xffffffffu, tsum,   off);
        }
        if (lane == 0) { redA[wid] = regsum; redB[wid] = tsum; }
        __syncthreads();
        if (tid == 0) {
            g_scal[0] = (redA[0]+redA[1]+redA[2]+redA[3]) * (1.0f / NBR);
            g_scal[1] = (redB[0]+redB[1]+redB[2]+redB[3]) * (1.0f / (BS*NPTS*3));
        }
    }

    // ================= grid-completion: last block finalizes =================
    __threadfence();
    if (tid == 0) {
        unsigned int ticket = atomicAdd(&g_cnt, 1u);
        s_last = (ticket == (unsigned)(NBR + 1) - 1u) ? 1 : 0;
    }
    __syncthreads();

    if (s_last) {
        float lr = 0.f;
        for (int i = tid; i < NBR; i += 128) {
            int b = i / NROT;
            float d = (symmetric[b] != 0) ? g_sym[i] : g_nonsym[i];
            float c = pred_c[i];
            lr += (d / (diameters[b] * c) + logf(c)) * (1.0f / NROT);
        }
        #pragma unroll
        for (int off = 16; off; off >>= 1)
            lr += __shfl_down_sync(0xffffffffu, lr, off);
        if (lane == 0) redA[wid] = lr;
        __syncthreads();
        if (tid == 0) {
            float lrt  = redA[0] + redA[1] + redA[2] + redA[3];
            float lreg = g_scal[0];
            float lt   = g_scal[1];
            out[0] = lrt + 2.f * lreg + 5.f * lt;
            out[1] = lrt;
            out[2] = lreg;
            out[3] = lt;
            g_cnt = 0;   // reset for next graph replay
        }
    }
}

// ---------------------------------------------------------------------------
// Launch. Input order: pred_t, pred_r, pred_c, target_r, target_t,
//                      model_points, choose, symmetric, diameters, rot_anchors
// ---------------------------------------------------------------------------
extern "C" void kernel_launch(void* const* d_in, const int* in_sizes, int n_in,
                              void* d_out, int out_size)
{
    fused_kernel<<<NBR + 1, 128>>>(
        (const float*)d_in[0], (const float*)d_in[1], (const float*)d_in[2],
        (const float*)d_in[3], (const float*)d_in[4], (const float*)d_in[5],
        (const int*)d_in[6],   (const int*)d_in[7],   (const float*)d_in[8],
        (const float*)d_in[9], (float*)d_out);
}

// round 9
// speedup vs baseline: 1.1143x; 1.1143x over previous
#include <cuda_runtime.h>
#include <math.h>

#define BS    8
#define NROT  60
#define NPTS  500
#define NBR   (BS * NROT)     // 480
#define HW    6400            // 80*80
#define CHUNK 5               // targets batched per load group (500 = 5*100)
#define TPB   256
#define NW    (TPB / 32)

// Scratch (allocation-free: __device__ globals)
__device__ float g_sym[NBR];
__device__ float g_nonsym[NBR];
__device__ float g_scal[2];       // [0] = loss_reg, [1] = loss_t
__device__ unsigned int g_cnt;    // completion counter (reset by last block)

// ---------------------------------------------------------------------------
// Single fused kernel, grid = NBR + 1 blocks of 256 threads.
//  blocks 0..479 : chamfer for one (b, r); 2 pred points per thread, scalar FFMA
//  block  480    : reg loss + huber translation loss (runs concurrently)
//  last block to finish: finalize loss_r and combine into out[0..3]
// ---------------------------------------------------------------------------
__global__ __launch_bounds__(TPB, 4) void fused_kernel(
    const float* __restrict__ pred_t,        // (8,500,3)
    const float* __restrict__ pred_r,        // (8,60,4)
    const float* __restrict__ pred_c,        // (8,60)
    const float* __restrict__ target_r,      // (8,1,500,3)
    const float* __restrict__ target_t,      // (8,3,80,80)
    const float* __restrict__ model_points,  // (8,1,500,3)
    const int*   __restrict__ choose,        // (8,500)
    const int*   __restrict__ symmetric,     // (8,) bool->int32
    const float* __restrict__ diameters,     // (8,)
    const float* __restrict__ rot_anchors,   // (60,4)
    float*       __restrict__ out)           // 4 floats
{
    __shared__ float4 tg[NPTS];    // per target: (-2tx, -2ty, -2tz, |t|^2)
    __shared__ float  redA[NW], redB[NW];
    __shared__ int    s_last;

    const int tid  = threadIdx.x;
    const int lane = tid & 31;
    const int wid  = tid >> 5;
    const int blk  = blockIdx.x;

    if (blk < NBR) {
        // ================= chamfer block =================
        const int b = blk / NROT;
        const float* tp = target_r + (size_t)b * NPTS * 3;

        for (int m = tid; m < NPTS; m += TPB) {
            float tx = tp[3*m], ty = tp[3*m+1], tz = tp[3*m+2];
            tg[m] = make_float4(-2.f*tx, -2.f*ty, -2.f*tz,
                                tx*tx + ty*ty + tz*tz);
        }

        // Rotation matrix from (unnormalized) quaternion, as reference.
        const float* q = pred_r + (size_t)blk * 4;
        float w = q[0], x = q[1], y = q[2], z = q[3];
        float r00 = 1.f - 2.f*(y*y + z*z);
        float r01 = 2.f*x*y - 2.f*w*z;
        float r02 = 2.f*w*y + 2.f*x*z;
        float r10 = 2.f*x*y + 2.f*z*w;
        float r11 = 1.f - 2.f*(x*x + z*z);
        float r12 = -2.f*w*x + 2.f*y*z;
        float r20 = -2.f*w*y + 2.f*x*z;
        float r21 = 2.f*w*x + 2.f*y*z;
        float r22 = 1.f - 2.f*(x*x + y*y);

        __syncthreads();

        // 2 pred points per thread: n = tid, tid + 256
        const float* mpb = model_points + (size_t)b * NPTS * 3;
        float px[2], py[2], pz[2], a2[2];
        bool  val[2];
        #pragma unroll
        for (int i = 0; i < 2; i++) {
            int n = tid + TPB * i;
            val[i] = (n < NPTS);
            float mx = 0.f, my = 0.f, mz = 0.f;
            if (val[i]) { mx = mpb[3*n]; my = mpb[3*n+1]; mz = mpb[3*n+2]; }
            px[i] = r00*mx + r01*my + r02*mz;
            py[i] = r10*mx + r11*my + r12*mz;
            pz[i] = r20*mx + r21*my + r22*mz;
            a2[i] = px[i]*px[i] + py[i]*py[i] + pz[i]*pz[i];
        }

        const float INF = 3.4e38f;
        // Two min accumulators per point (chunk parity) to break FMNMX chains.
        float mnA[2] = {INF, INF};
        float mnB[2] = {INF, INF};

        // Scalar inner loop: per target 1 LDS.128 + 2x(3 FFMA + 1 FMNMX).
        for (int j0 = 0; j0 < NPTS; j0 += CHUNK) {
            float4 T[CHUNK];
            #pragma unroll
            for (int k = 0; k < CHUNK; k++) T[k] = tg[j0 + k];
            #pragma unroll
            for (int k = 0; k < CHUNK; k++) {
                #pragma unroll
                for (int i = 0; i < 2; i++) {
                    float s = fmaf(px[i], T[k].x,
                              fmaf(py[i], T[k].y,
                              fmaf(pz[i], T[k].z, T[k].w)));
                    if (k & 1) mnB[i] = fminf(mnB[i], s);
                    else       mnA[i] = fminf(mnA[i], s);
                }
            }
        }

        float symsum = 0.f, nssum = 0.f;
        #pragma unroll
        for (int i = 0; i < 2; i++) {
            if (val[i]) {
                float m = fminf(mnA[i], mnB[i]);
                symsum += sqrtf(fmaxf(a2[i] + m, 1e-12f));
                int n = tid + TPB * i;
                // recover t_n from tg: t = -0.5 * tg.xyz
                float4 t = tg[n];
                float dx = fmaf(0.5f, t.x, px[i]);
                float dy = fmaf(0.5f, t.y, py[i]);
                float dz = fmaf(0.5f, t.z, pz[i]);
                nssum += sqrtf(dx*dx + dy*dy + dz*dz);
            }
        }

        #pragma unroll
        for (int off = 16; off; off >>= 1) {
            symsum += __shfl_down_sync(0xffffffffu, symsum, off);
            nssum  += __shfl_down_sync(0xffffffffu, nssum,  off);
        }
        if (lane == 0) { redA[wid] = symsum; redB[wid] = nssum; }
        __syncthreads();
        if (tid == 0) {
            float sa = 0.f, sb = 0.f;
            #pragma unroll
            for (int k = 0; k < NW; k++) { sa += redA[k]; sb += redB[k]; }
            g_sym[blk]    = sa * (1.0f / NPTS);
            g_nonsym[blk] = sb * (1.0f / NPTS);
        }
    } else {
        // ================= reg + huber block =================
        float* anc = reinterpret_cast<float*>(tg);  // 240 floats
        for (int i = tid; i < NROT * 4; i += TPB) anc[i] = rot_anchors[i];
        __syncthreads();

        float regsum = 0.f;
        for (int i = tid; i < NBR; i += TPB) {
            int r = i % NROT;
            float q0 = pred_r[4*i], q1 = pred_r[4*i+1];
            float q2 = pred_r[4*i+2], q3 = pred_r[4*i+3];
            float mx = -3.4e38f, dg = 0.f;
            #pragma unroll 4
            for (int a = 0; a < NROT; a++) {
                float c = q0*anc[4*a] + q1*anc[4*a+1] + q2*anc[4*a+2] + q3*anc[4*a+3];
                mx = fmaxf(mx, c);
                if (a == r) dg = c;
            }
            float reg = mx - dg;
            regsum += (reg > 0.001f) ? reg : 0.f;
        }

        float tsum = 0.f;
        for (int i = tid; i < BS * NPTS; i += TPB) {
            int b  = i / NPTS;
            int ch = choose[i];
            const float* tb = target_t + (size_t)b * 3 * HW;
            float tv0 = tb[ch], tv1 = tb[HW + ch], tv2 = tb[2*HW + ch];
            float p0 = pred_t[3*i], p1 = pred_t[3*i+1], p2 = pred_t[3*i+2];
            float d0 = p0 - tv0, d1 = p1 - tv1, d2 = p2 - tv2;
            float a0 = fabsf(d0), a1 = fabsf(d1), a2v = fabsf(d2);
            tsum += (a0 < 1.f) ? 0.5f*d0*d0 : (a0 - 0.5f);
            tsum += (a1 < 1.f) ? 0.5f*d1*d1 : (a1 - 0.5f);
            tsum += (a2v < 1.f) ? 0.5f*d2*d2 : (a2v - 0.5f);
        }

        #pragma unroll
        for (int off = 16; off; off >>= 1) {
            regsum += __shfl_down_sync(0xffffffffu, regsum, off);
            tsum   += __shfl_down_sync(0xffffffffu, tsum,   off);
        }
        if (lane == 0) { redA[wid] = regsum; redB[wid] = tsum; }
        __syncthreads();
        if (tid == 0) {
            float sa = 0.f, sb = 0.f;
            #pragma unroll
            for (int k = 0; k < NW; k++) { sa += redA[k]; sb += redB[k]; }
            g_scal[0] = sa * (1.0f / NBR);
            g_scal[1] = sb * (1.0f / (BS*NPTS*3));
        }
    }

    // ================= grid-completion: last block finalizes =================
    __threadfence();
    if (tid == 0) {
        unsigned int ticket = atomicAdd(&g_cnt, 1u);
        s_last = (ticket == (unsigned)(NBR + 1) - 1u) ? 1 : 0;
    }
    __syncthreads();

    if (s_last) {
        float lr = 0.f;
        for (int i = tid; i < NBR; i += TPB) {
            int b = i / NROT;
            float d = (symmetric[b] != 0) ? g_sym[i] : g_nonsym[i];
            float c = pred_c[i];
            lr += (d / (diameters[b] * c) + logf(c)) * (1.0f / NROT);
        }
        #pragma unroll
        for (int off = 16; off; off >>= 1)
            lr += __shfl_down_sync(0xffffffffu, lr, off);
        if (lane == 0) redA[wid] = lr;
        __syncthreads();
        if (tid == 0) {
            float lrt = 0.f;
            #pragma unroll
            for (int k = 0; k < NW; k++) lrt += redA[k];
            float lreg = g_scal[0];
            float lt   = g_scal[1];
            out[0] = lrt + 2.f * lreg + 5.f * lt;
            out[1] = lrt;
            out[2] = lreg;
            out[3] = lt;
            g_cnt = 0;   // reset for next graph replay
        }
    }
}

// ---------------------------------------------------------------------------
// Launch. Input order: pred_t, pred_r, pred_c, target_r, target_t,
//                      model_points, choose, symmetric, diameters, rot_anchors
// ---------------------------------------------------------------------------
extern "C" void kernel_launch(void* const* d_in, const int* in_sizes, int n_in,
                              void* d_out, int out_size)
{
    fused_kernel<<<NBR + 1, TPB>>>(
        (const float*)d_in[0], (const float*)d_in[1], (const float*)d_in[2],
        (const float*)d_in[3], (const float*)d_in[4], (const float*)d_in[5],
        (const int*)d_in[6],   (const int*)d_in[7],   (const float*)d_in[8],
        (const float*)d_in[9], (float*)d_out);
}